// round 6
// baseline (speedup 1.0000x reference)
#include <cuda_runtime.h>

// noiseRNN: h_t = tanh(W_ih x_t + b_ih + W_hh h_{t-1} + b_hh); carry h_t + 0.1*noise_t
// T=2048, B=256, I=64, H=128. 128 blocks x 2 batches, persistent over T steps.
// 512 threads (16 warps): warp w -> k-slice (w&7)*24, j-half (w>>3)*64.
// Thread: 2 j-rows x 24 k x 2 batches in registers, packed f32x2 FMAs.
// Phase 2: tid<256 reduce 8 partials + fast tanh + write z; tid 256..383 stage next x.

#define T_STEPS 2048
#define BATCH   256
#define IN_DIM  64
#define HID     128
#define KDIM    192
#define STD_F   0.1f
#define THREADS 512

__device__ __forceinline__ unsigned long long fma2(unsigned long long a,
                                                   unsigned long long b,
                                                   unsigned long long c) {
    unsigned long long d;
    asm("fma.rn.f32x2 %0, %1, %2, %3;" : "=l"(d) : "l"(a), "l"(b), "l"(c));
    return d;
}
__device__ __forceinline__ unsigned long long packf2(float lo, float hi) {
    return (unsigned long long)__float_as_uint(lo) |
           ((unsigned long long)__float_as_uint(hi) << 32);
}
__device__ __forceinline__ float lo_f(unsigned long long v) {
    return __uint_as_float((unsigned)v);
}
__device__ __forceinline__ float hi_f(unsigned long long v) {
    return __uint_as_float((unsigned)(v >> 32));
}
// tanh(s) = 1 - 2/(exp(2s)+1): 2x MUFU + 4 fp ops, ~1e-6 accuracy.
__device__ __forceinline__ float fast_tanh(float s) {
    float e = __expf(2.0f * s);
    return 1.0f - __fdividef(2.0f, e + 1.0f);
}

__global__ void __launch_bounds__(THREADS, 1) noise_rnn_kernel(
    const float* __restrict__ x,         // [T,B,I]
    const float* __restrict__ w_ih,      // [H,I]
    const float* __restrict__ w_hh,      // [H,H]
    const float* __restrict__ b_ih,      // [H]
    const float* __restrict__ b_hh,      // [H]
    const float* __restrict__ noise,     // [T,B,H]
    const float* __restrict__ hidden_in, // [1,B,H]
    float* __restrict__ out,             // [T,B,H] (+ [1,B,H] h_last)
    int out_size)
{
    __shared__ __align__(16) float zA[KDIM];
    __shared__ __align__(16) float padA[4];        // bank-shift zB vs zA
    __shared__ __align__(16) float zB[KDIM];
    __shared__ __align__(16) float psh[8 * 256];   // [k-slice][b*128 + j]
    (void)padA;

    const int tid  = threadIdx.x;
    const int lane = tid & 31;
    const int warp = tid >> 5;
    const int bb   = blockIdx.x * 2;

    // matvec role
    const int kq    = warp & 7;          // k-slice index
    const int jh    = warp >> 3;         // j-half
    const int jbase = jh * 64 + lane * 2;
    const int ks    = kq * 24;

    // reduction role (tid < 256): tid = rb*128 + rj
    const bool isRed = tid < 256;
    const int rb = (tid >> 7) & 1;
    const int rj = tid & 127;
    const int gb = bb + rb;
    float* const zr = rb ? zB : zA;

    // x-stager role (tid in [256,384))
    const bool isX  = (tid >= 256) && (tid < 384);
    const int  xi   = tid - 256;
    const int  rbx  = xi >> 6;
    const int  xidx = xi & 63;
    const int  gbx  = bb + rbx;
    float* const zx = rbx ? zB : zA;

    // --- weights: W_cat[j][k] = k<HID ? w_hh[j][k] : w_ih[j][k-HID], k-pair packed ---
    unsigned long long wpk[2][12];
#pragma unroll
    for (int p = 0; p < 12; ++p) {
        const int k0 = ks + 2 * p;
        const int k1 = k0 + 1;
#pragma unroll
        for (int jj = 0; jj < 2; ++jj) {
            const int j = jbase + jj;
            const float lo = (k0 < HID) ? w_hh[j * HID + k0]
                                        : w_ih[j * IN_DIM + (k0 - HID)];
            const float hi = (k1 < HID) ? w_hh[j * HID + k1]
                                        : w_ih[j * IN_DIM + (k1 - HID)];
            wpk[jj][p] = packf2(lo, hi);
        }
    }

    const float bias_r = isRed ? (b_ih[rj] + b_hh[rj]) : 0.0f;

    // --- init z(t=0) ---
    if (isRed) zr[rj] = hidden_in[gb * HID + rj];
    if (isX)   zx[HID + xidx] = x[gbx * IN_DIM + xidx];
    __syncthreads();

    const int nb_base  = gb * HID + rj;    // noise/out offset within a step
    const int x_base   = gbx * IN_DIM + xidx;

    for (int t = 0; t < T_STEPS; ++t) {
        // prefetch (consumed ~400 cycles later, after the matvec)
        const float nz = isRed ? noise[t * (BATCH * HID) + nb_base] : 0.0f;
        const bool  ldx = isX && (t + 1 < T_STEPS);
        float xn = 0.0f;
        if (ldx) xn = x[(t + 1) * (BATCH * IN_DIM) + x_base];

        // --- matvec partials: 2 j-rows x 24 k x 2 batches ---
        unsigned long long aA0 = 0ull, aA1 = 0ull, aB0 = 0ull, aB1 = 0ull;
        const ulonglong2* zap = reinterpret_cast<const ulonglong2*>(zA + ks);
        const ulonglong2* zbp = reinterpret_cast<const ulonglong2*>(zB + ks);
#pragma unroll
        for (int q = 0; q < 6; ++q) {
            const ulonglong2 va = zap[q];   // broadcast LDS.128 (warp-uniform addr)
            const ulonglong2 vb = zbp[q];
            const unsigned long long w0 = wpk[0][2 * q];
            const unsigned long long w1 = wpk[0][2 * q + 1];
            const unsigned long long w2 = wpk[1][2 * q];
            const unsigned long long w3 = wpk[1][2 * q + 1];
            aA0 = fma2(w0, va.x, aA0);  aA0 = fma2(w1, va.y, aA0);
            aA1 = fma2(w2, va.x, aA1);  aA1 = fma2(w3, va.y, aA1);
            aB0 = fma2(w0, vb.x, aB0);  aB0 = fma2(w1, vb.y, aB0);
            aB1 = fma2(w2, vb.x, aB1);  aB1 = fma2(w3, vb.y, aB1);
        }

        // horizontal combine + store partials (batch-major: [kq][b*128 + j])
        {
            float2 pA, pB;
            pA.x = lo_f(aA0) + hi_f(aA0);
            pA.y = lo_f(aA1) + hi_f(aA1);
            pB.x = lo_f(aB0) + hi_f(aB0);
            pB.y = lo_f(aB1) + hi_f(aB1);
            *reinterpret_cast<float2*>(psh + kq * 256 + jbase)       = pA;
            *reinterpret_cast<float2*>(psh + kq * 256 + 128 + jbase) = pB;
        }
        __syncthreads();

        // --- reduce + activation + state update ---
        if (isRed) {
            const float p0 = psh[0 * 256 + tid];
            const float p1 = psh[1 * 256 + tid];
            const float p2 = psh[2 * 256 + tid];
            const float p3 = psh[3 * 256 + tid];
            const float p4 = psh[4 * 256 + tid];
            const float p5 = psh[5 * 256 + tid];
            const float p6 = psh[6 * 256 + tid];
            const float p7 = psh[7 * 256 + tid];
            const float s01 = p0 + p1, s23 = p2 + p3;
            const float s45 = p4 + p5, s67 = p6 + p7;
            const float s = ((s01 + s23) + (s45 + s67)) + bias_r;

            const float hn = fast_tanh(s);
            out[t * (BATCH * HID) + nb_base] = hn;

            const float zn = hn + STD_F * nz;   // noisy carried state
            zr[rj] = zn;

            if (t == T_STEPS - 1 && out_size > T_STEPS * BATCH * HID)
                out[T_STEPS * (BATCH * HID) + nb_base] = zn;   // h_last
        }
        if (ldx) zx[HID + xidx] = xn;           // stage next x
        __syncthreads();
    }
}

extern "C" void kernel_launch(void* const* d_in, const int* in_sizes, int n_in,
                              void* d_out, int out_size) {
    const float* x         = (const float*)d_in[0];
    const float* w_ih      = (const float*)d_in[1];
    const float* w_hh      = (const float*)d_in[2];
    const float* b_ih      = (const float*)d_in[3];
    const float* b_hh      = (const float*)d_in[4];
    const float* noise     = (const float*)d_in[5];
    const float* hidden_in = (const float*)d_in[6];
    float* out = (float*)d_out;

    noise_rnn_kernel<<<BATCH / 2, THREADS>>>(x, w_ih, w_hh, b_ih, b_hh,
                                             noise, hidden_in, out, out_size);
}

// round 7
// speedup vs baseline: 1.2597x; 1.2597x over previous
#include <cuda_runtime.h>

// noiseRNN: h_t = tanh(W_ih x_t + b_ih + W_hh h_{t-1} + b_hh); carry h_t + 0.1*noise_t
// T=2048, B=256, I=64, H=128.
// 256 blocks x 128 threads, 1 batch per block, 2 CTAs/SM (independent barrier
// domains overlap each other's serial tails). Each thread owns one output row j
// with the FULL K=192 weight row in registers (96 packed f32x2) -> no partial
// reduction at all. z=[h;x_t] broadcast from SMEM via warp-uniform LDS.128.

#define T_STEPS 2048
#define BATCH   256
#define IN_DIM  64
#define HID     128
#define KDIM    192
#define STD_F   0.1f

__device__ __forceinline__ unsigned long long fma2(unsigned long long a,
                                                   unsigned long long b,
                                                   unsigned long long c) {
    unsigned long long d;
    asm("fma.rn.f32x2 %0, %1, %2, %3;" : "=l"(d) : "l"(a), "l"(b), "l"(c));
    return d;
}
__device__ __forceinline__ unsigned long long packf2(float lo, float hi) {
    return (unsigned long long)__float_as_uint(lo) |
           ((unsigned long long)__float_as_uint(hi) << 32);
}
__device__ __forceinline__ float lo_f(unsigned long long v) {
    return __uint_as_float((unsigned)v);
}
__device__ __forceinline__ float hi_f(unsigned long long v) {
    return __uint_as_float((unsigned)(v >> 32));
}
// tanh(s) = 1 - 2/(exp(2s)+1): 2 MUFU + 4 fp ops, ~1e-6 accuracy.
__device__ __forceinline__ float fast_tanh(float s) {
    float e = __expf(2.0f * s);
    return 1.0f - __fdividef(2.0f, e + 1.0f);
}

__global__ void __launch_bounds__(128, 2) noise_rnn_kernel(
    const float* __restrict__ x,         // [T,B,I]
    const float* __restrict__ w_ih,      // [H,I]
    const float* __restrict__ w_hh,      // [H,H]
    const float* __restrict__ b_ih,      // [H]
    const float* __restrict__ b_hh,      // [H]
    const float* __restrict__ noise,     // [T,B,H]
    const float* __restrict__ hidden_in, // [1,B,H]
    float* __restrict__ out,             // [T,B,H] (+ [1,B,H] h_last)
    int out_size)
{
    __shared__ __align__(16) float z[KDIM];   // [h(128); x_t(64)]

    const int j = threadIdx.x;   // output row 0..127
    const int b = blockIdx.x;    // batch

    // --- full weight row in registers, k-pair packed: k<HID -> w_hh, else w_ih ---
    unsigned long long wpk[96];
    {
        const float* whr = w_hh + j * HID;
        const float* wir = w_ih + j * IN_DIM;
#pragma unroll
        for (int p = 0; p < 64; ++p)
            wpk[p] = packf2(whr[2 * p], whr[2 * p + 1]);
#pragma unroll
        for (int p = 0; p < 32; ++p)
            wpk[64 + p] = packf2(wir[2 * p], wir[2 * p + 1]);
    }

    const float bias = b_ih[j] + b_hh[j];

    // --- init z(t=0) ---
    z[j] = hidden_in[b * HID + j];
    if (j < IN_DIM) z[HID + j] = x[b * IN_DIM + j];
    __syncthreads();

    const int nb = b * HID + j;      // noise/out per-step offset
    const int xb = b * IN_DIM + j;   // x per-step offset (j < 64 only)

    for (int t = 0; t < T_STEPS; ++t) {
        // prefetch: consumed after the ~400-cycle matvec
        const float nz = noise[t * (BATCH * HID) + nb];
        const bool ldx = (j < IN_DIM) && (t + 1 < T_STEPS);
        float xn = 0.0f;
        if (ldx) xn = x[(t + 1) * (BATCH * IN_DIM) + xb];

        // --- full-K dot product: 96 fma2, 4 independent chains ---
        unsigned long long a0 = 0ull, a1 = 0ull, a2 = 0ull, a3 = 0ull;
        const ulonglong2* zq = reinterpret_cast<const ulonglong2*>(z);
#pragma unroll
        for (int i = 0; i < 48; ++i) {
            const ulonglong2 v = zq[i];     // warp-uniform broadcast LDS.128
            if (i & 1) {
                a1 = fma2(wpk[2 * i],     v.x, a1);
                a3 = fma2(wpk[2 * i + 1], v.y, a3);
            } else {
                a0 = fma2(wpk[2 * i],     v.x, a0);
                a2 = fma2(wpk[2 * i + 1], v.y, a2);
            }
        }
        const float s = ((lo_f(a0) + hi_f(a0)) + (lo_f(a1) + hi_f(a1)))
                      + ((lo_f(a2) + hi_f(a2)) + (lo_f(a3) + hi_f(a3))) + bias;

        const float hn = fast_tanh(s);
        out[t * (BATCH * HID) + nb] = hn;
        const float zn = hn + STD_F * nz;    // noisy carried state

        __syncthreads();                     // everyone done READING z
        z[j] = zn;
        if (ldx) z[HID + j] = xn;            // stage next x
        if (t == T_STEPS - 1 && out_size > T_STEPS * BATCH * HID)
            out[T_STEPS * (BATCH * HID) + nb] = zn;   // h_last
        __syncthreads();                     // writes visible for next step
    }
}

extern "C" void kernel_launch(void* const* d_in, const int* in_sizes, int n_in,
                              void* d_out, int out_size) {
    const float* x         = (const float*)d_in[0];
    const float* w_ih      = (const float*)d_in[1];
    const float* w_hh      = (const float*)d_in[2];
    const float* b_ih      = (const float*)d_in[3];
    const float* b_hh      = (const float*)d_in[4];
    const float* noise     = (const float*)d_in[5];
    const float* hidden_in = (const float*)d_in[6];
    float* out = (float*)d_out;

    noise_rnn_kernel<<<BATCH, 128>>>(x, w_ih, w_hh, b_ih, b_hh,
                                     noise, hidden_in, out, out_size);
}